// round 7
// baseline (speedup 1.0000x reference)
#include <cuda_runtime.h>
#include <cuda_fp16.h>
#include <math.h>
#include <stdint.h>

// NT-Xent loss on GB300. Hybrid tensor+SIMT GEMM:
// legacy mma.sync pipe is MAC-capped (~260 MAC/cyc/SM, dtype-independent,
// measured R4/R5/R6), so each CTA adds 4 HFMA2 SIMT warps (fma pipe, +128
// MAC/cyc/SM) beside 8 HMMA warps. Tile 128x128: HMMA does cols 0..95,
// SIMT does cols 96..127. Upper-triangle symmetry (2080 of 4096 tiles).

#define NROWS 8192
#define NC    512
#define BHALF 4096
#define NB    (NROWS / 128)         // 64
#define NPAIRS (NB * (NB + 1) / 2)  // 2080

#define BM 128
#define BK 64
#define KITERS (NC / BK)            // 8
#define NSTAGE 3
#define STAGE_BYTES (2 * BM * BK * 2)      // 32768
#define SMEM_TOTAL (NSTAGE * STAGE_BYTES)  // 98304
#define NTHREADS 384

__device__ __align__(1024) __half g_zn[(size_t)NROWS * NC];
__device__ float g_pos[BHALF];
__device__ float g_rs[(size_t)NROWS * NB];

__device__ __forceinline__ uint32_t smem_u32(const void* p) {
    uint32_t a;
    asm("{ .reg .u64 t; cvta.to.shared.u64 t, %1; cvt.u32.u64 %0, t; }"
        : "=r"(a) : "l"(p));
    return a;
}

#define CP_ASYNC16(dst, src) \
    asm volatile("cp.async.cg.shared.global [%0], [%1], 16;" :: "r"(dst), "l"(src) : "memory")
#define CP_COMMIT() asm volatile("cp.async.commit_group;" ::: "memory")

#define LDSM_X4(r0, r1, r2, r3, addr)                                          \
    asm volatile("ldmatrix.sync.aligned.m8n8.x4.shared.b16 {%0,%1,%2,%3}, [%4];" \
                 : "=r"(r0), "=r"(r1), "=r"(r2), "=r"(r3) : "r"(addr))
#define LDSM_X2(r0, r1, addr)                                                  \
    asm volatile("ldmatrix.sync.aligned.m8n8.x2.shared.b16 {%0,%1}, [%2];"     \
                 : "=r"(r0), "=r"(r1) : "r"(addr))
#define LDS128(r0, r1, r2, r3, addr)                                           \
    asm volatile("ld.shared.v4.u32 {%0,%1,%2,%3}, [%4];"                       \
                 : "=r"(r0), "=r"(r1), "=r"(r2), "=r"(r3) : "r"(addr))

#define MMAF16(c, a0, a1, a2, a3, b0, b1)                                      \
    asm volatile("mma.sync.aligned.m16n8k16.row.col.f16.f16.f16.f16 "          \
                 "{%0,%1},{%2,%3,%4,%5},{%6,%7},{%0,%1};"                      \
                 : "+r"((c)[0]), "+r"((c)[1])                                  \
                 : "r"(a0), "r"(a1), "r"(a2), "r"(a3), "r"(b0), "r"(b1))

// ---------------------------------------------------------------------------
// Kernel 1: L2-normalize rows, emit fp16 z
// ---------------------------------------------------------------------------
__global__ void normalize_kernel(const float* __restrict__ z1,
                                 const float* __restrict__ z2) {
    int r = blockIdx.x;
    const float* row = (r < BHALF) ? (z1 + (size_t)r * NC)
                                   : (z2 + (size_t)(r - BHALF) * NC);
    int t = threadIdx.x;
    float4 v = ((const float4*)row)[t];
    float s = v.x * v.x + v.y * v.y + v.z * v.z + v.w * v.w;
#pragma unroll
    for (int o = 16; o; o >>= 1) s += __shfl_xor_sync(0xFFFFFFFFu, s, o);
    __shared__ float ws[4];
    if ((t & 31) == 0) ws[t >> 5] = s;
    __syncthreads();
    s = ws[0] + ws[1] + ws[2] + ws[3];
    float inv = 1.0f / fmaxf(sqrtf(s), 1e-12f);
    __half2 lo = __floats2half2_rn(v.x * inv, v.y * inv);
    __half2 hi = __floats2half2_rn(v.z * inv, v.w * inv);
    __half2* dst = (__half2*)g_zn + (size_t)r * (NC / 2) + t * 2;
    dst[0] = lo;
    dst[1] = hi;
}

// ---------------------------------------------------------------------------
// Kernel 2: hybrid fused GEMM + exp + row/col sums + positive capture.
// Warps 0-7: HMMA (2M x 4N, warp tile 64x24, cols 0..95).
// Warps 8-11: SIMT HFMA2 (warp w-8 owns rows (w-8)*32..+31, cols 96..127).
// ---------------------------------------------------------------------------
__global__ __launch_bounds__(NTHREADS, 2) void gemm_kernel() {
    extern __shared__ __align__(1024) char smem[];
    const int tid = threadIdx.x;
    const int lane = tid & 31;
    const int w = tid >> 5;

    // map linear block id -> upper-triangle pair (bm <= bn)
    int rem = blockIdx.x;
    int bm = 0;
#pragma unroll 1
    while (rem >= (NB - bm)) { rem -= (NB - bm); bm++; }
    const int bn = bm + rem;
    const int r0 = bm * BM;
    const int c0 = bn * BM;
    const uint32_t sbase = smem_u32(smem);

    // ---- cp.async loaders: threads 0..255 -> 256 tile rows (128 A + 128 B) -
    const int isld = (tid < 256);
    const int half = (tid >> 7) & 1;
    const int lrow = tid & 127;
    const char* grow = (const char*)g_zn +
        ((size_t)((half ? c0 : r0) + lrow)) * (NC * 2);
    const uint32_t sdst = sbase + (uint32_t)half * (BM * BK * 2) +
                          (uint32_t)lrow * 128u;
    const uint32_t xr = ((uint32_t)lrow & 7u) << 4;

#define ISSUE_STAGE(s_)                                                        \
    do { if (isld) {                                                           \
        const char* g_ = grow + (s_) * (BK * 2);                               \
        uint32_t d_ = sdst + (uint32_t)((s_) % NSTAGE) * STAGE_BYTES;          \
        _Pragma("unroll")                                                      \
        for (int c_ = 0; c_ < 8; c_++)                                         \
            CP_ASYNC16(d_ + (((uint32_t)c_ * 16u) ^ xr), g_ + c_ * 16);        \
        CP_COMMIT();                                                           \
    } } while (0)

    ISSUE_STAGE(0);
    ISSUE_STAGE(1);

    if (w < 8) {
        // ================= HMMA path: cols 0..95 =================
        const int wm = w >> 2;
        const int wn = w & 3;

        uint32_t addrA[4], xA[4];
        const uint32_t chunkA = ((uint32_t)(lane >> 4)) * 16u;
#pragma unroll
        for (int mi = 0; mi < 4; mi++) {
            int rA = wm * 64 + mi * 16 + (lane & 15);
            addrA[mi] = sbase + (uint32_t)rA * 128u;
            xA[mi] = ((uint32_t)rA & 7u) << 4;
        }
        const uint32_t chunkB = ((uint32_t)((lane >> 3) & 1)) * 16u;
        int rB4 = wn * 24 + ((lane >> 4) & 1) * 8 + (lane & 7);
        uint32_t addrB4 = sbase + (uint32_t)(BM * BK * 2) + (uint32_t)rB4 * 128u;
        uint32_t xB4 = ((uint32_t)rB4 & 7u) << 4;
        int rB2 = wn * 24 + 16 + (lane & 7);
        uint32_t addrB2 = sbase + (uint32_t)(BM * BK * 2) + (uint32_t)rB2 * 128u;
        uint32_t xB2 = ((uint32_t)rB2 & 7u) << 4;

        uint32_t acc[4][3][2];
#pragma unroll
        for (int mi = 0; mi < 4; mi++)
#pragma unroll
            for (int ni = 0; ni < 3; ni++) {
                acc[mi][ni][0] = 0u;
                acc[mi][ni][1] = 0u;
            }

#pragma unroll 1
        for (int i = 0; i < KITERS; i++) {
            if (i < KITERS - 1)
                asm volatile("cp.async.wait_group 1;" ::: "memory");
            else
                asm volatile("cp.async.wait_group 0;" ::: "memory");
            __syncthreads();
            if (i + 2 < KITERS) ISSUE_STAGE(i + 2);

            const uint32_t sb = (uint32_t)(i % NSTAGE) * STAGE_BYTES;
#pragma unroll
            for (int kk = 0; kk < 4; kk++) {
                const uint32_t kkb = (uint32_t)kk * 32u;
                uint32_t a[4][4], b4[4], b2[2];
#pragma unroll
                for (int mi = 0; mi < 4; mi++)
                    LDSM_X4(a[mi][0], a[mi][1], a[mi][2], a[mi][3],
                            addrA[mi] + sb + ((kkb | chunkA) ^ xA[mi]));
                LDSM_X4(b4[0], b4[1], b4[2], b4[3],
                        addrB4 + sb + ((kkb | chunkB) ^ xB4));
                LDSM_X2(b2[0], b2[1],
                        addrB2 + sb + ((kkb | chunkB) ^ xB2));
#pragma unroll
                for (int mi = 0; mi < 4; mi++) {
                    MMAF16(acc[mi][0], a[mi][0], a[mi][1], a[mi][2], a[mi][3],
                           b4[0], b4[1]);
                    MMAF16(acc[mi][1], a[mi][0], a[mi][1], a[mi][2], a[mi][3],
                           b4[2], b4[3]);
                    MMAF16(acc[mi][2], a[mi][0], a[mi][1], a[mi][2], a[mi][3],
                           b2[0], b2[1]);
                }
            }
        }

        // ---- HMMA epilogue ----
        float vr[4][2];   // row partials [mi][h]
        float cv[3][2];   // col partials [ni][parity]
#pragma unroll
        for (int i = 0; i < 4; i++) { vr[i][0] = vr[i][1] = 0.f; }
#pragma unroll
        for (int i = 0; i < 3; i++) { cv[i][0] = cv[i][1] = 0.f; }

#pragma unroll
        for (int mi = 0; mi < 4; mi++)
#pragma unroll
            for (int ni = 0; ni < 3; ni++)
#pragma unroll
                for (int h = 0; h < 2; h++) {
                    float2 f = __half22float2(*(__half2*)&acc[mi][ni][h]);
                    int rowg = r0 + wm * 64 + mi * 16 + h * 8 + (lane >> 2);
                    int colb = c0 + wn * 24 + ni * 8 + (lane & 3) * 2;
                    float v0 = __expf(f.x * 10.0f);
                    float v1 = __expf(f.y * 10.0f);
                    vr[mi][h] += v0 + v1;
                    cv[ni][0] += v0;
                    cv[ni][1] += v1;
                    if (colb == rowg + BHALF) g_pos[rowg] = v0;
                    if (colb + 1 == rowg + BHALF) g_pos[rowg] = v1;
                }
#pragma unroll
        for (int mi = 0; mi < 4; mi++)
#pragma unroll
            for (int h = 0; h < 2; h++) {
                float v = vr[mi][h];
                v += __shfl_xor_sync(0xFFFFFFFFu, v, 1);
                v += __shfl_xor_sync(0xFFFFFFFFu, v, 2);
                vr[mi][h] = v;
            }
#pragma unroll
        for (int ni = 0; ni < 3; ni++)
#pragma unroll
            for (int b = 0; b < 2; b++) {
                float v = cv[ni][b];
                v += __shfl_xor_sync(0xFFFFFFFFu, v, 4);
                v += __shfl_xor_sync(0xFFFFFFFFu, v, 8);
                v += __shfl_xor_sync(0xFFFFFFFFu, v, 16);
                cv[ni][b] = v;
            }

        __syncthreads();   // stage buffers dead; smem becomes reduction arrays
        float* redr = (float*)smem;            // [5][128]
        float* redc_h = (float*)smem + 640;    // [2][96]
        if ((lane & 3) == 0) {
#pragma unroll
            for (int mi = 0; mi < 4; mi++)
#pragma unroll
                for (int h = 0; h < 2; h++)
                    redr[wn * 128 + wm * 64 + mi * 16 + h * 8 + (lane >> 2)] =
                        vr[mi][h];
        }
        if (lane < 4) {
#pragma unroll
            for (int ni = 0; ni < 3; ni++)
#pragma unroll
                for (int b = 0; b < 2; b++)
                    redc_h[wm * 96 + wn * 24 + ni * 8 + lane * 2 + b] = cv[ni][b];
        }
    } else {
        // ================= SIMT HFMA2 path: cols 96..127 =================
        const int sw = w - 8;
        __half2 accS[8][4];
#pragma unroll
        for (int i = 0; i < 8; i++)
#pragma unroll
            for (int j = 0; j < 4; j++)
                accS[i][j] = __floats2half2_rn(0.f, 0.f);

        const uint32_t aRowB = sbase +
            (uint32_t)(sw * 32 + (lane & 3)) * 128u;
        const uint32_t bRowB = sbase + (uint32_t)(BM * BK * 2) +
            (uint32_t)(96 + (lane >> 2)) * 128u;
        const uint32_t swzE = ((uint32_t)(lane & 3)) << 4;
        const uint32_t swzO = ((uint32_t)((lane & 3) + 4)) << 4;
        const uint32_t swzB = ((uint32_t)(lane >> 2)) << 4;

#pragma unroll 1
        for (int i = 0; i < KITERS; i++) {
            asm volatile("cp.async.wait_group 0;" ::: "memory");  // no own groups
            __syncthreads();
            // loaders issue stage i+2 inside their branch; nothing here

            const uint32_t sb = (uint32_t)(i % NSTAGE) * STAGE_BYTES;
#pragma unroll
            for (int kc = 0; kc < 8; kc++) {
                const uint32_t kcb = (uint32_t)kc * 16u;
                uint32_t ar[8][4];
#pragma unroll
                for (int ii = 0; ii < 8; ii++) {
                    uint32_t sw_ = (ii & 1) ? swzO : swzE;
                    LDS128(ar[ii][0], ar[ii][1], ar[ii][2], ar[ii][3],
                           aRowB + sb + (uint32_t)ii * 512u + (kcb ^ sw_));
                }
#pragma unroll
                for (int j = 0; j < 4; j++) {
                    uint32_t br[4];
                    LDS128(br[0], br[1], br[2], br[3],
                           bRowB + sb + (uint32_t)j * 1024u + (kcb ^ swzB));
#pragma unroll
                    for (int ii = 0; ii < 8; ii++)
#pragma unroll
                        for (int p = 0; p < 4; p++)
                            accS[ii][j] = __hfma2(*(__half2*)&ar[ii][p],
                                                  *(__half2*)&br[p],
                                                  accS[ii][j]);
                }
            }
        }

        // ---- SIMT epilogue ----
        float rs[8], cs[4];
#pragma unroll
        for (int i = 0; i < 8; i++) rs[i] = 0.f;
#pragma unroll
        for (int j = 0; j < 4; j++) cs[j] = 0.f;
#pragma unroll
        for (int i = 0; i < 8; i++)
#pragma unroll
            for (int j = 0; j < 4; j++) {
                float2 f = __half22float2(accS[i][j]);
                float v = __expf((f.x + f.y) * 10.0f);
                rs[i] += v;
                cs[j] += v;
                int rowg = r0 + sw * 32 + (lane & 3) + i * 4;
                int col = c0 + 96 + (lane >> 2) + j * 8;
                if (col == rowg + BHALF) g_pos[rowg] = v;
            }
        // rows: reduce over lanes sharing row (lane>>2 varies)
#pragma unroll
        for (int i = 0; i < 8; i++) {
            float v = rs[i];
            v += __shfl_xor_sync(0xFFFFFFFFu, v, 4);
            v += __shfl_xor_sync(0xFFFFFFFFu, v, 8);
            v += __shfl_xor_sync(0xFFFFFFFFu, v, 16);
            rs[i] = v;
        }
        // cols: reduce over lanes sharing col (lane&3 varies)
#pragma unroll
        for (int j = 0; j < 4; j++) {
            float v = cs[j];
            v += __shfl_xor_sync(0xFFFFFFFFu, v, 1);
            v += __shfl_xor_sync(0xFFFFFFFFu, v, 2);
            cs[j] = v;
        }

        __syncthreads();
        float* redr = (float*)smem;            // [5][128]
        float* redc_s = (float*)smem + 832;    // [4][32]
        if (lane < 4) {
#pragma unroll
            for (int i = 0; i < 8; i++)
                redr[4 * 128 + sw * 32 + lane + i * 4] = rs[i];
        }
        if ((lane & 3) == 0) {
#pragma unroll
            for (int j = 0; j < 4; j++)
                redc_s[sw * 32 + (lane >> 2) + j * 8] = cs[j];
        }
    }

    __syncthreads();
    float* redr = (float*)smem;
    float* redc_h = (float*)smem + 640;
    float* redc_s = (float*)smem + 832;
    if (tid < 128) {
        float t = redr[tid] + redr[128 + tid] + redr[256 + tid] +
                  redr[384 + tid] + redr[512 + tid];
        g_rs[((size_t)(r0 + tid)) * NB + bn] = t;
    } else if (tid < 256 && bm != bn) {
        int c = tid - 128;
        float t;
        if (c < 96) {
            t = redc_h[c] + redc_h[96 + c];
        } else {
            int cc = c - 96;
            t = redc_s[cc] + redc_s[32 + cc] + redc_s[64 + cc] + redc_s[96 + cc];
        }
        g_rs[((size_t)(c0 + c)) * NB + bm] = t;
    }
}

// ---------------------------------------------------------------------------
// Kernel 3: loss = sum_r [log(rowsum_r - pos_r) - log(pos_r)] / (N*B)
// ---------------------------------------------------------------------------
__global__ void loss_kernel(float* __restrict__ out) {
    __shared__ float ws[8];
    float s = 0.f;
    for (int r = threadIdx.x; r < NROWS; r += blockDim.x) {
        const float4* p4 = (const float4*)&g_rs[(size_t)r * NB];
        float tot = 0.f;
#pragma unroll
        for (int i = 0; i < NB / 4; i++) {
            float4 q = p4[i];
            tot += (q.x + q.y) + (q.z + q.w);
        }
        float p = g_pos[r & (BHALF - 1)];
        s += logf(tot - p) - logf(p);
    }
#pragma unroll
    for (int o = 16; o; o >>= 1) s += __shfl_xor_sync(0xFFFFFFFFu, s, o);
    if ((threadIdx.x & 31) == 0) ws[threadIdx.x >> 5] = s;
    __syncthreads();
    if (threadIdx.x < 8) {
        float v = ws[threadIdx.x];
#pragma unroll
        for (int o = 4; o; o >>= 1) v += __shfl_xor_sync(0xFFu, v, o);
        if (threadIdx.x == 0)
            out[0] = v / ((float)NROWS * (float)BHALF);
    }
}

extern "C" void kernel_launch(void* const* d_in, const int* in_sizes, int n_in,
                              void* d_out, int out_size) {
    const float* z1 = (const float*)d_in[0];
    const float* z2 = (const float*)d_in[1];
    (void)in_sizes; (void)n_in; (void)out_size;

    cudaFuncSetAttribute(gemm_kernel, cudaFuncAttributeMaxDynamicSharedMemorySize,
                         SMEM_TOTAL);

    normalize_kernel<<<NROWS, 128>>>(z1, z2);
    gemm_kernel<<<NPAIRS, NTHREADS, SMEM_TOTAL>>>();
    loss_kernel<<<1, 256>>>((float*)d_out);
}

// round 8
// speedup vs baseline: 1.0221x; 1.0221x over previous
#include <cuda_runtime.h>
#include <cuda_fp16.h>
#include <math.h>
#include <stdint.h>

// NT-Xent loss on GB300. Uniform-warp hybrid GEMM:
// legacy mma.sync tensor pipe is capped at 64 MAC/cyc/SMSP (rt 32 per
// m16n8k16, measured R4-R6). Each of the 8 warps does HMMA for cols 0..95
// AND HFMA2 (fma pipe, otherwise idle) for cols 96..127 of the 128x128 tile.
// Upper-triangle symmetry: 2080 of 4096 tiles; off-diagonal tiles emit row
// sums and column sums. SIMT f16 accumulation drained to fp32 every stage.

#define NROWS 8192
#define NC    512
#define BHALF 4096
#define NB    (NROWS / 128)         // 64
#define NPAIRS (NB * (NB + 1) / 2)  // 2080

#define BM 128
#define BK 64
#define KITERS (NC / BK)            // 8
#define NSTAGE 3
#define STAGE_BYTES (2 * BM * BK * 2)      // 32768
#define SMEM_TOTAL (NSTAGE * STAGE_BYTES)  // 98304

__device__ __align__(1024) __half g_zn[(size_t)NROWS * NC];
__device__ float g_pos[BHALF];
__device__ float g_rs[(size_t)NROWS * NB];

__device__ __forceinline__ uint32_t smem_u32(const void* p) {
    uint32_t a;
    asm("{ .reg .u64 t; cvta.to.shared.u64 t, %1; cvt.u32.u64 %0, t; }"
        : "=r"(a) : "l"(p));
    return a;
}

#define CP_ASYNC16(dst, src) \
    asm volatile("cp.async.cg.shared.global [%0], [%1], 16;" :: "r"(dst), "l"(src) : "memory")
#define CP_COMMIT() asm volatile("cp.async.commit_group;" ::: "memory")

#define LDSM_X4(r0, r1, r2, r3, addr)                                          \
    asm volatile("ldmatrix.sync.aligned.m8n8.x4.shared.b16 {%0,%1,%2,%3}, [%4];" \
                 : "=r"(r0), "=r"(r1), "=r"(r2), "=r"(r3) : "r"(addr))
#define LDSM_X2(r0, r1, addr)                                                  \
    asm volatile("ldmatrix.sync.aligned.m8n8.x2.shared.b16 {%0,%1}, [%2];"     \
                 : "=r"(r0), "=r"(r1) : "r"(addr))
#define LDS128(r0, r1, r2, r3, addr)                                           \
    asm volatile("ld.shared.v4.u32 {%0,%1,%2,%3}, [%4];"                       \
                 : "=r"(r0), "=r"(r1), "=r"(r2), "=r"(r3) : "r"(addr))

#define MMAF16(c, a0, a1, a2, a3, b0, b1)                                      \
    asm volatile("mma.sync.aligned.m16n8k16.row.col.f16.f16.f16.f16 "          \
                 "{%0,%1},{%2,%3,%4,%5},{%6,%7},{%0,%1};"                      \
                 : "+r"((c)[0]), "+r"((c)[1])                                  \
                 : "r"(a0), "r"(a1), "r"(a2), "r"(a3), "r"(b0), "r"(b1))

#define HFMA2(d, a, b)                                                         \
    asm volatile("fma.rn.f16x2 %0, %1, %2, %0;" : "+r"(d) : "r"(a), "r"(b))

// ---------------------------------------------------------------------------
// Kernel 1: L2-normalize rows, emit fp16 z
// ---------------------------------------------------------------------------
__global__ void normalize_kernel(const float* __restrict__ z1,
                                 const float* __restrict__ z2) {
    int r = blockIdx.x;
    const float* row = (r < BHALF) ? (z1 + (size_t)r * NC)
                                   : (z2 + (size_t)(r - BHALF) * NC);
    int t = threadIdx.x;
    float4 v = ((const float4*)row)[t];
    float s = v.x * v.x + v.y * v.y + v.z * v.z + v.w * v.w;
#pragma unroll
    for (int o = 16; o; o >>= 1) s += __shfl_xor_sync(0xFFFFFFFFu, s, o);
    __shared__ float ws[4];
    if ((t & 31) == 0) ws[t >> 5] = s;
    __syncthreads();
    s = ws[0] + ws[1] + ws[2] + ws[3];
    float inv = 1.0f / fmaxf(sqrtf(s), 1e-12f);
    __half2 lo = __floats2half2_rn(v.x * inv, v.y * inv);
    __half2 hi = __floats2half2_rn(v.z * inv, v.w * inv);
    __half2* dst = (__half2*)g_zn + (size_t)r * (NC / 2) + t * 2;
    dst[0] = lo;
    dst[1] = hi;
}

// ---------------------------------------------------------------------------
// Kernel 2: hybrid fused GEMM + exp + row/col sums + positive capture.
// 8 warps, each: HMMA warp tile 64x24 (2M x 4N grid, cols 0..95) plus a
// SIMT HFMA2 slice of cols 96..127 (thread tile 4 rows x 4 cols).
// ---------------------------------------------------------------------------
__global__ __launch_bounds__(256, 2) void gemm_kernel() {
    extern __shared__ __align__(1024) char smem[];
    const int tid = threadIdx.x;
    const int lane = tid & 31;
    const int w = tid >> 5;
    const int wm = w >> 2;       // 0..1
    const int wn = w & 3;        // 0..3

    // map linear block id -> upper-triangle pair (bm <= bn)
    int rem = blockIdx.x;
    int bm = 0;
#pragma unroll 1
    while (rem >= (NB - bm)) { rem -= (NB - bm); bm++; }
    const int bn = bm + rem;
    const int r0 = bm * BM;
    const int c0 = bn * BM;
    const uint32_t sbase = smem_u32(smem);

    // ---- cp.async mapping: 256 threads -> 256 tile rows (128 A + 128 B) ----
    const int half = tid >> 7;
    const int lrow = tid & 127;
    const char* grow = (const char*)g_zn +
        ((size_t)((half ? c0 : r0) + lrow)) * (NC * 2);
    const uint32_t sdst = sbase + (uint32_t)half * (BM * BK * 2) +
                          (uint32_t)lrow * 128u;
    const uint32_t xr = ((uint32_t)lrow & 7u) << 4;

#define ISSUE_STAGE(s_)                                                        \
    do {                                                                       \
        const char* g_ = grow + (s_) * (BK * 2);                               \
        uint32_t d_ = sdst + (uint32_t)((s_) % NSTAGE) * STAGE_BYTES;          \
        _Pragma("unroll")                                                      \
        for (int c_ = 0; c_ < 8; c_++)                                         \
            CP_ASYNC16(d_ + (((uint32_t)c_ * 16u) ^ xr), g_ + c_ * 16);        \
        CP_COMMIT();                                                           \
    } while (0)

    ISSUE_STAGE(0);
    ISSUE_STAGE(1);

    // ---- HMMA ldmatrix addresses (warp tile 64x24) ----
    uint32_t addrA[4], xA[4];
    const uint32_t chunkA = ((uint32_t)(lane >> 4)) * 16u;
#pragma unroll
    for (int mi = 0; mi < 4; mi++) {
        int rA = wm * 64 + mi * 16 + (lane & 15);
        addrA[mi] = sbase + (uint32_t)rA * 128u;
        xA[mi] = ((uint32_t)rA & 7u) << 4;
    }
    const uint32_t chunkB = ((uint32_t)((lane >> 3) & 1)) * 16u;
    int rB4 = wn * 24 + ((lane >> 4) & 1) * 8 + (lane & 7);
    uint32_t addrB4 = sbase + (uint32_t)(BM * BK * 2) + (uint32_t)rB4 * 128u;
    uint32_t xB4 = ((uint32_t)rB4 & 7u) << 4;
    int rB2 = wn * 24 + 16 + (lane & 7);
    uint32_t addrB2 = sbase + (uint32_t)(BM * BK * 2) + (uint32_t)rB2 * 128u;
    uint32_t xB2 = ((uint32_t)rB2 & 7u) << 4;

    // ---- SIMT slice addresses (cols 96..127, rows rg+32i) ----
    const int c8 = lane & 7;                     // col group
    const int rg = (w << 2) | ((lane >> 3) & 3); // row group 0..31
    const uint32_t swzA = ((uint32_t)(rg & 7)) << 4;
    const uint32_t swzB = ((uint32_t)c8) << 4;
    const uint32_t aBase = sbase + (uint32_t)rg * 128u;               // +i*4096
    const uint32_t bBase = sbase + (uint32_t)(BM * BK * 2) +
                           (uint32_t)(96 + c8) * 128u;                // +j*1024

    uint32_t acc[4][3][2];     // HMMA f16x2 accumulators
#pragma unroll
    for (int mi = 0; mi < 4; mi++)
#pragma unroll
        for (int ni = 0; ni < 3; ni++) {
            acc[mi][ni][0] = 0u;
            acc[mi][ni][1] = 0u;
        }
    float acc32[4][4];         // SIMT fp32 accumulators
#pragma unroll
    for (int i = 0; i < 4; i++)
#pragma unroll
        for (int j = 0; j < 4; j++) acc32[i][j] = 0.f;

    // ---- mainloop ----
#pragma unroll 1
    for (int it = 0; it < KITERS; it++) {
        if (it < KITERS - 1)
            asm volatile("cp.async.wait_group 1;" ::: "memory");
        else
            asm volatile("cp.async.wait_group 0;" ::: "memory");
        __syncthreads();
        if (it + 2 < KITERS) ISSUE_STAGE(it + 2);

        const uint32_t sb = (uint32_t)(it % NSTAGE) * STAGE_BYTES;

        uint32_t accH[4][4];   // SIMT f16x2 stage accumulators
#pragma unroll
        for (int i = 0; i < 4; i++)
#pragma unroll
            for (int j = 0; j < 4; j++) accH[i][j] = 0u;

#pragma unroll
        for (int kk = 0; kk < 4; kk++) {
            const uint32_t kkb = (uint32_t)kk * 32u;
            // HMMA: B fragments for this k16
            uint32_t b4[4], b2[2];
            LDSM_X4(b4[0], b4[1], b4[2], b4[3],
                    addrB4 + sb + ((kkb | chunkB) ^ xB4));
            LDSM_X2(b2[0], b2[1],
                    addrB2 + sb + ((kkb | chunkB) ^ xB2));
#pragma unroll
            for (int mi = 0; mi < 4; mi++) {
                uint32_t a0, a1, a2, a3;
                LDSM_X4(a0, a1, a2, a3,
                        addrA[mi] + sb + ((kkb | chunkA) ^ xA[mi]));
                MMAF16(acc[mi][0], a0, a1, a2, a3, b4[0], b4[1]);
                MMAF16(acc[mi][1], a0, a1, a2, a3, b4[2], b4[3]);
                MMAF16(acc[mi][2], a0, a1, a2, a3, b2[0], b2[1]);
            }
            // SIMT: two k8 chunks for this k16
#pragma unroll
            for (int h = 0; h < 2; h++) {
                const uint32_t koff = kkb + (uint32_t)h * 16u;
                uint32_t aq[4][4];
#pragma unroll
                for (int i = 0; i < 4; i++)
                    LDS128(aq[i][0], aq[i][1], aq[i][2], aq[i][3],
                           aBase + sb + (uint32_t)i * 4096u + (koff ^ swzA));
#pragma unroll
                for (int j = 0; j < 4; j++) {
                    uint32_t bq[4];
                    LDS128(bq[0], bq[1], bq[2], bq[3],
                           bBase + sb + (uint32_t)j * 1024u + (koff ^ swzB));
#pragma unroll
                    for (int i = 0; i < 4; i++) {
                        HFMA2(accH[i][j], aq[i][0], bq[0]);
                        HFMA2(accH[i][j], aq[i][1], bq[1]);
                        HFMA2(accH[i][j], aq[i][2], bq[2]);
                        HFMA2(accH[i][j], aq[i][3], bq[3]);
                    }
                }
            }
        }
        // drain SIMT stage accumulators to fp32
#pragma unroll
        for (int i = 0; i < 4; i++)
#pragma unroll
            for (int j = 0; j < 4; j++) {
                float2 f = __half22float2(*(__half2*)&accH[i][j]);
                acc32[i][j] += f.x + f.y;
            }
    }

    // ================= epilogue =================
    // ---- HMMA part (cols 0..95) ----
    float vr[4][2];   // row partials [mi][h]
    float cv[3][2];   // col partials [ni][parity]
#pragma unroll
    for (int i = 0; i < 4; i++) { vr[i][0] = vr[i][1] = 0.f; }
#pragma unroll
    for (int i = 0; i < 3; i++) { cv[i][0] = cv[i][1] = 0.f; }

#pragma unroll
    for (int mi = 0; mi < 4; mi++)
#pragma unroll
        for (int ni = 0; ni < 3; ni++)
#pragma unroll
            for (int h = 0; h < 2; h++) {
                float2 f = __half22float2(*(__half2*)&acc[mi][ni][h]);
                int rowg = r0 + wm * 64 + mi * 16 + h * 8 + (lane >> 2);
                int colb = c0 + wn * 24 + ni * 8 + (lane & 3) * 2;
                float v0 = __expf(f.x * 10.0f);
                float v1 = __expf(f.y * 10.0f);
                vr[mi][h] += v0 + v1;
                cv[ni][0] += v0;
                cv[ni][1] += v1;
                if (colb == rowg + BHALF) g_pos[rowg] = v0;
                if (colb + 1 == rowg + BHALF) g_pos[rowg] = v1;
            }
#pragma unroll
    for (int mi = 0; mi < 4; mi++)
#pragma unroll
        for (int h = 0; h < 2; h++) {
            float v = vr[mi][h];
            v += __shfl_xor_sync(0xFFFFFFFFu, v, 1);
            v += __shfl_xor_sync(0xFFFFFFFFu, v, 2);
            vr[mi][h] = v;
        }
#pragma unroll
    for (int ni = 0; ni < 3; ni++)
#pragma unroll
        for (int b = 0; b < 2; b++) {
            float v = cv[ni][b];
            v += __shfl_xor_sync(0xFFFFFFFFu, v, 4);
            v += __shfl_xor_sync(0xFFFFFFFFu, v, 8);
            v += __shfl_xor_sync(0xFFFFFFFFu, v, 16);
            cv[ni][b] = v;
        }

    // ---- SIMT part (cols 96..127) ----
    float rsS[4];   // row sums for rows rg+32i (over this thread's 4 cols)
    float csS[4];   // col sums for cols 96+c8+8j (over this thread's 4 rows)
#pragma unroll
    for (int i = 0; i < 4; i++) { rsS[i] = 0.f; csS[i] = 0.f; }
#pragma unroll
    for (int i = 0; i < 4; i++)
#pragma unroll
        for (int j = 0; j < 4; j++) {
            float v = __expf(acc32[i][j] * 10.0f);
            rsS[i] += v;
            csS[j] += v;
            int rowg = r0 + rg + 32 * i;
            int colg = c0 + 96 + c8 + 8 * j;
            if (colg == rowg + BHALF) g_pos[rowg] = v;
        }
    // row sums: reduce over c8 (lane bits 0..2)
#pragma unroll
    for (int i = 0; i < 4; i++) {
        float v = rsS[i];
        v += __shfl_xor_sync(0xFFFFFFFFu, v, 1);
        v += __shfl_xor_sync(0xFFFFFFFFu, v, 2);
        v += __shfl_xor_sync(0xFFFFFFFFu, v, 4);
        rsS[i] = v;
    }
    // col sums: reduce over rg-within-warp (lane bits 3..4)
#pragma unroll
    for (int j = 0; j < 4; j++) {
        float v = csS[j];
        v += __shfl_xor_sync(0xFFFFFFFFu, v, 8);
        v += __shfl_xor_sync(0xFFFFFFFFu, v, 16);
        csS[j] = v;
    }

    __syncthreads();   // stage buffers dead; smem becomes reduction arrays
    float* redr = (float*)smem;            // [5][128] row partials
    float* redc_h = (float*)smem + 640;    // [2][96]  HMMA col partials
    float* redc_s = (float*)smem + 832;    // [8][32]  SIMT col partials
    if ((lane & 3) == 0) {
#pragma unroll
        for (int mi = 0; mi < 4; mi++)
#pragma unroll
            for (int h = 0; h < 2; h++)
                redr[wn * 128 + wm * 64 + mi * 16 + h * 8 + (lane >> 2)] =
                    vr[mi][h];
    }
    if (lane < 4) {
#pragma unroll
        for (int ni = 0; ni < 3; ni++)
#pragma unroll
            for (int b = 0; b < 2; b++)
                redc_h[wm * 96 + wn * 24 + ni * 8 + lane * 2 + b] = cv[ni][b];
    }
    if ((lane & 7) == 0) {
#pragma unroll
        for (int i = 0; i < 4; i++)
            redr[4 * 128 + rg + 32 * i] = rsS[i];
    }
    if (lane < 8) {
#pragma unroll
        for (int j = 0; j < 4; j++)
            redc_s[w * 32 + c8 + 8 * j] = csS[j];
    }
    __syncthreads();
    if (tid < 128) {
        float t = redr[tid] + redr[128 + tid] + redr[256 + tid] +
                  redr[384 + tid] + redr[512 + tid];
        g_rs[((size_t)(r0 + tid)) * NB + bn] = t;
    } else if (bm != bn) {
        int c = tid - 128;
        float t;
        if (c < 96) {
            t = redc_h[c] + redc_h[96 + c];
        } else {
            int cc = c - 96;
            t = 0.f;
#pragma unroll
            for (int ww = 0; ww < 8; ww++) t += redc_s[ww * 32 + cc];
        }
        g_rs[((size_t)(c0 + c)) * NB + bm] = t;
    }
}

// ---------------------------------------------------------------------------
// Kernel 3: loss = sum_r [log(rowsum_r - pos_r) - log(pos_r)] / (N*B)
// ---------------------------------------------------------------------------
__global__ void loss_kernel(float* __restrict__ out) {
    __shared__ float ws[8];
    float s = 0.f;
    for (int r = threadIdx.x; r < NROWS; r += blockDim.x) {
        const float4* p4 = (const float4*)&g_rs[(size_t)r * NB];
        float tot = 0.f;
#pragma unroll
        for (int i = 0; i < NB / 4; i++) {
            float4 q = p4[i];
            tot += (q.x + q.y) + (q.z + q.w);
        }
        float p = g_pos[r & (BHALF - 1)];
        s += logf(tot - p) - logf(p);
    }
#pragma unroll
    for (int o = 16; o; o >>= 1) s += __shfl_xor_sync(0xFFFFFFFFu, s, o);
    if ((threadIdx.x & 31) == 0) ws[threadIdx.x >> 5] = s;
    __syncthreads();
    if (threadIdx.x < 8) {
        float v = ws[threadIdx.x];
#pragma unroll
        for (int o = 4; o; o >>= 1) v += __shfl_xor_sync(0xFFu, v, o);
        if (threadIdx.x == 0)
            out[0] = v / ((float)NROWS * (float)BHALF);
    }
}

extern "C" void kernel_launch(void* const* d_in, const int* in_sizes, int n_in,
                              void* d_out, int out_size) {
    const float* z1 = (const float*)d_in[0];
    const float* z2 = (const float*)d_in[1];
    (void)in_sizes; (void)n_in; (void)out_size;

    cudaFuncSetAttribute(gemm_kernel, cudaFuncAttributeMaxDynamicSharedMemorySize,
                         SMEM_TOTAL);

    normalize_kernel<<<NROWS, 128>>>(z1, z2);
    gemm_kernel<<<NPAIRS, 256, SMEM_TOTAL>>>();
    loss_kernel<<<1, 256>>>((float*)d_out);
}

// round 9
// speedup vs baseline: 1.4083x; 1.3778x over previous
#include <cuda_runtime.h>
#include <cuda_fp16.h>
#include <math.h>
#include <stdint.h>

// NT-Xent loss on GB300, f16-acc HMMA + symmetry + fine-grained 64x64 tiles.
// Legacy mma.sync is MAC-capped (~256 MAC/cyc/SM, shape/dtype independent;
// R4/R5/R6 evidence) and does NOT stack with the fma pipe (R7/R8 evidence).
// So the remaining lever is scheduling efficiency: 64x64 tiles -> 8256 CTAs
// at occupancy 4 -> 13.95 ideal waves vs 14 actual = 99.6% utilization
// (vs 87.8% for 128x128 tiles at occ 2).

#define NROWS 8192
#define NC    512
#define BHALF 4096
#define NB    (NROWS / 64)            // 128 blocks per dim
#define NTILE (NB * (NB + 1) / 2)     // 8256 upper-triangle tiles

#define BT 64                          // tile dim (rows and cols)
#define BK 64
#define KITERS (NC / BK)               // 8
#define NSTAGE 3
#define STAGE_BYTES (2 * BT * BK * 2)  // A + B = 16384
#define SMEM_TOTAL (NSTAGE * STAGE_BYTES)  // 49152

__device__ __align__(1024) __half g_zn[(size_t)NROWS * NC];
__device__ float g_pos[BHALF];
__device__ float g_rs[(size_t)NROWS * NB];   // [row][other 64-block]
__device__ float g_part[64];

__device__ __forceinline__ uint32_t smem_u32(const void* p) {
    uint32_t a;
    asm("{ .reg .u64 t; cvta.to.shared.u64 t, %1; cvt.u32.u64 %0, t; }"
        : "=r"(a) : "l"(p));
    return a;
}

#define CP_ASYNC16(dst, src) \
    asm volatile("cp.async.cg.shared.global [%0], [%1], 16;" :: "r"(dst), "l"(src) : "memory")
#define CP_COMMIT() asm volatile("cp.async.commit_group;" ::: "memory")

#define LDSM_X4(r0, r1, r2, r3, addr)                                          \
    asm volatile("ldmatrix.sync.aligned.m8n8.x4.shared.b16 {%0,%1,%2,%3}, [%4];" \
                 : "=r"(r0), "=r"(r1), "=r"(r2), "=r"(r3) : "r"(addr))

#define MMAF16(c, a0, a1, a2, a3, b0, b1)                                      \
    asm volatile("mma.sync.aligned.m16n8k16.row.col.f16.f16.f16.f16 "          \
                 "{%0,%1},{%2,%3,%4,%5},{%6,%7},{%0,%1};"                      \
                 : "+r"((c)[0]), "+r"((c)[1])                                  \
                 : "r"(a0), "r"(a1), "r"(a2), "r"(a3), "r"(b0), "r"(b1))

// ---------------------------------------------------------------------------
// Kernel 1: L2-normalize rows, emit fp16 z
// ---------------------------------------------------------------------------
__global__ void normalize_kernel(const float* __restrict__ z1,
                                 const float* __restrict__ z2) {
    int r = blockIdx.x;
    const float* row = (r < BHALF) ? (z1 + (size_t)r * NC)
                                   : (z2 + (size_t)(r - BHALF) * NC);
    int t = threadIdx.x;
    float4 v = ((const float4*)row)[t];
    float s = v.x * v.x + v.y * v.y + v.z * v.z + v.w * v.w;
#pragma unroll
    for (int o = 16; o; o >>= 1) s += __shfl_xor_sync(0xFFFFFFFFu, s, o);
    __shared__ float ws[4];
    if ((t & 31) == 0) ws[t >> 5] = s;
    __syncthreads();
    s = ws[0] + ws[1] + ws[2] + ws[3];
    float inv = 1.0f / fmaxf(sqrtf(s), 1e-12f);
    __half2 lo = __floats2half2_rn(v.x * inv, v.y * inv);
    __half2 hi = __floats2half2_rn(v.z * inv, v.w * inv);
    __half2* dst = (__half2*)g_zn + (size_t)r * (NC / 2) + t * 2;
    dst[0] = lo;
    dst[1] = hi;
}

// ---------------------------------------------------------------------------
// Kernel 2: fused GEMM + exp + row/col sums + positive capture.
// 64x64 tile, 128 threads = 4 warps (2M x 2N), warp tile 32x32 (m16n8k16).
// ---------------------------------------------------------------------------
__global__ __launch_bounds__(128, 4) void gemm_kernel() {
    extern __shared__ __align__(1024) char smem[];
    const int tid = threadIdx.x;
    const int lane = tid & 31;
    const int w = tid >> 5;
    const int wm = w >> 1;       // 0..1
    const int wn = w & 1;        // 0..1

    // map linear block id -> upper-triangle pair (bm <= bn) over 128 blocks
    int rem = blockIdx.x;
    int bm = 0;
#pragma unroll 1
    while (rem >= (NB - bm)) { rem -= (NB - bm); bm++; }
    const int bn = bm + rem;
    const int r0 = bm * BT;
    const int c0 = bn * BT;
    const uint32_t sbase = smem_u32(smem);

    // ---- cp.async: 128 threads -> 128 tile rows (64 A + 64 B), 128B each ---
    const int half = tid >> 6;
    const int lrow = tid & 63;
    const char* grow = (const char*)g_zn +
        ((size_t)((half ? c0 : r0) + lrow)) * (NC * 2);
    const uint32_t sdst = sbase + (uint32_t)tid * 128u;
    const uint32_t xr = ((uint32_t)tid & 7u) << 4;

#define ISSUE_STAGE(s_)                                                        \
    do {                                                                       \
        const char* g_ = grow + (s_) * (BK * 2);                               \
        uint32_t d_ = sdst + (uint32_t)((s_) % NSTAGE) * STAGE_BYTES;          \
        _Pragma("unroll")                                                      \
        for (int c_ = 0; c_ < 8; c_++)                                         \
            CP_ASYNC16(d_ + (((uint32_t)c_ * 16u) ^ xr), g_ + c_ * 16);        \
        CP_COMMIT();                                                           \
    } while (0)

    ISSUE_STAGE(0);
    ISSUE_STAGE(1);

    // ---- ldmatrix addresses (warp tile 32x32) ----
    uint32_t addrA[2], xA[2];
    const uint32_t chunkA = ((uint32_t)(lane >> 4)) * 16u;
#pragma unroll
    for (int mi = 0; mi < 2; mi++) {
        int rA = wm * 32 + mi * 16 + (lane & 15);
        addrA[mi] = sbase + (uint32_t)rA * 128u;
        xA[mi] = ((uint32_t)rA & 7u) << 4;
    }
    uint32_t addrB[2], xB[2];
    const uint32_t chunkB = ((uint32_t)((lane >> 3) & 1)) * 16u;
#pragma unroll
    for (int np = 0; np < 2; np++) {
        int rB = wn * 32 + np * 16 + ((lane >> 4) & 1) * 8 + (lane & 7);
        addrB[np] = sbase + (uint32_t)(BT * BK * 2) + (uint32_t)rB * 128u;
        xB[np] = ((uint32_t)rB & 7u) << 4;
    }

    uint32_t acc[2][4][2];   // f16x2 accumulators
#pragma unroll
    for (int mi = 0; mi < 2; mi++)
#pragma unroll
        for (int ni = 0; ni < 4; ni++) {
            acc[mi][ni][0] = 0u;
            acc[mi][ni][1] = 0u;
        }

    // ---- mainloop ----
#pragma unroll 1
    for (int i = 0; i < KITERS; i++) {
        if (i < KITERS - 1)
            asm volatile("cp.async.wait_group 1;" ::: "memory");
        else
            asm volatile("cp.async.wait_group 0;" ::: "memory");
        __syncthreads();
        if (i + 2 < KITERS) ISSUE_STAGE(i + 2);

        const uint32_t sb = (uint32_t)(i % NSTAGE) * STAGE_BYTES;
#pragma unroll
        for (int kk = 0; kk < 4; kk++) {
            const uint32_t kkb = (uint32_t)kk * 32u;
            uint32_t a[2][4], b[2][4];
#pragma unroll
            for (int mi = 0; mi < 2; mi++)
                LDSM_X4(a[mi][0], a[mi][1], a[mi][2], a[mi][3],
                        addrA[mi] + sb + ((kkb | chunkA) ^ xA[mi]));
#pragma unroll
            for (int np = 0; np < 2; np++)
                LDSM_X4(b[np][0], b[np][1], b[np][2], b[np][3],
                        addrB[np] + sb + ((kkb | chunkB) ^ xB[np]));
#pragma unroll
            for (int mi = 0; mi < 2; mi++)
#pragma unroll
                for (int ni = 0; ni < 4; ni++)
                    MMAF16(acc[mi][ni],
                           a[mi][0], a[mi][1], a[mi][2], a[mi][3],
                           b[ni >> 1][(ni & 1) * 2],
                           b[ni >> 1][(ni & 1) * 2 + 1]);
        }
    }

    // ---- epilogue: promote, exp, positive capture, row/col partials ----
    float vr[2][2];   // row partials [mi][h]
    float cv[4][2];   // col partials [ni][parity]
#pragma unroll
    for (int i = 0; i < 2; i++) { vr[i][0] = vr[i][1] = 0.f; }
#pragma unroll
    for (int i = 0; i < 4; i++) { cv[i][0] = cv[i][1] = 0.f; }

#pragma unroll
    for (int mi = 0; mi < 2; mi++)
#pragma unroll
        for (int ni = 0; ni < 4; ni++)
#pragma unroll
            for (int h = 0; h < 2; h++) {
                float2 f = __half22float2(*(__half2*)&acc[mi][ni][h]);
                int rowg = r0 + wm * 32 + mi * 16 + h * 8 + (lane >> 2);
                int colb = c0 + wn * 32 + ni * 8 + (lane & 3) * 2;
                float v0 = __expf(f.x * 10.0f);
                float v1 = __expf(f.y * 10.0f);
                vr[mi][h] += v0 + v1;
                cv[ni][0] += v0;
                cv[ni][1] += v1;
                if (colb == rowg + BHALF) g_pos[rowg] = v0;
                if (colb + 1 == rowg + BHALF) g_pos[rowg] = v1;
            }
#pragma unroll
    for (int mi = 0; mi < 2; mi++)
#pragma unroll
        for (int h = 0; h < 2; h++) {
            float v = vr[mi][h];
            v += __shfl_xor_sync(0xFFFFFFFFu, v, 1);
            v += __shfl_xor_sync(0xFFFFFFFFu, v, 2);
            vr[mi][h] = v;
        }
#pragma unroll
    for (int ni = 0; ni < 4; ni++)
#pragma unroll
        for (int b = 0; b < 2; b++) {
            float v = cv[ni][b];
            v += __shfl_xor_sync(0xFFFFFFFFu, v, 4);
            v += __shfl_xor_sync(0xFFFFFFFFu, v, 8);
            v += __shfl_xor_sync(0xFFFFFFFFu, v, 16);
            cv[ni][b] = v;
        }

    __syncthreads();   // stage buffers dead; reuse smem for reductions
    float* redr = (float*)smem;          // [2 wn][64 rows]
    float* redc = (float*)smem + 128;    // [2 wm][64 cols]
    if ((lane & 3) == 0) {
#pragma unroll
        for (int mi = 0; mi < 2; mi++)
#pragma unroll
            for (int h = 0; h < 2; h++)
                redr[wn * 64 + wm * 32 + mi * 16 + h * 8 + (lane >> 2)] =
                    vr[mi][h];
    }
    if (lane < 4) {
#pragma unroll
        for (int ni = 0; ni < 4; ni++)
#pragma unroll
            for (int b = 0; b < 2; b++)
                redc[wm * 64 + wn * 32 + ni * 8 + lane * 2 + b] = cv[ni][b];
    }
    __syncthreads();
    if (tid < 64) {
        float t = redr[tid] + redr[64 + tid];
        g_rs[((size_t)(r0 + tid)) * NB + bn] = t;
    } else if (bm != bn) {
        int c = tid - 64;
        float t = redc[c] + redc[64 + c];
        g_rs[((size_t)(c0 + c)) * NB + bm] = t;
    }
}

// ---------------------------------------------------------------------------
// Kernel 3a: per-128-row partial loss sums (64 blocks, deterministic)
// ---------------------------------------------------------------------------
__global__ void loss_part_kernel() {
    int r = blockIdx.x * 128 + threadIdx.x;
    const float4* p4 = (const float4*)&g_rs[(size_t)r * NB];
    float tot = 0.f;
#pragma unroll
    for (int i = 0; i < NB / 4; i++) {
        float4 q = p4[i];
        tot += (q.x + q.y) + (q.z + q.w);
    }
    float p = g_pos[r & (BHALF - 1)];
    float s = logf(tot - p) - logf(p);
#pragma unroll
    for (int o = 16; o; o >>= 1) s += __shfl_xor_sync(0xFFFFFFFFu, s, o);
    __shared__ float ws[4];
    if ((threadIdx.x & 31) == 0) ws[threadIdx.x >> 5] = s;
    __syncthreads();
    if (threadIdx.x == 0)
        g_part[blockIdx.x] = ws[0] + ws[1] + ws[2] + ws[3];
}

// ---------------------------------------------------------------------------
// Kernel 3b: final scalar
// ---------------------------------------------------------------------------
__global__ void loss_final_kernel(float* __restrict__ out) {
    float s = g_part[threadIdx.x] + g_part[threadIdx.x + 32];
#pragma unroll
    for (int o = 16; o; o >>= 1) s += __shfl_xor_sync(0xFFFFFFFFu, s, o);
    if (threadIdx.x == 0)
        out[0] = s / ((float)NROWS * (float)BHALF);
}

extern "C" void kernel_launch(void* const* d_in, const int* in_sizes, int n_in,
                              void* d_out, int out_size) {
    const float* z1 = (const float*)d_in[0];
    const float* z2 = (const float*)d_in[1];
    (void)in_sizes; (void)n_in; (void)out_size;

    cudaFuncSetAttribute(gemm_kernel, cudaFuncAttributeMaxDynamicSharedMemorySize,
                         SMEM_TOTAL);

    normalize_kernel<<<NROWS, 128>>>(z1, z2);
    gemm_kernel<<<NTILE, 128, SMEM_TOTAL>>>();
    loss_part_kernel<<<64, 128>>>();
    loss_final_kernel<<<1, 32>>>((float*)d_out);
}

// round 10
// speedup vs baseline: 2.0219x; 1.4357x over previous
#include <cuda_runtime.h>
#include <cuda_fp16.h>
#include <math.h>
#include <stdint.h>

// NT-Xent loss on GB300, f16-acc HMMA + symmetry (R6 GEMM, at the measured
// legacy-pipe MAC cap of 64 MAC/cyc/SMSP) + overhead shaving:
// faster normalize (MLP 2, 8 rows/block) and fused loss reduction
// (last-block finalize). GEMM kernel is byte-identical to the 252us R6 one.

#define NROWS 8192
#define NC    512
#define BHALF 4096
#define NB    (NROWS / 128)         // 64
#define NPAIRS (NB * (NB + 1) / 2)  // 2080

#define BM 128
#define BN 128
#define BK 64
#define KITERS (NC / BK)        // 8
#define NSTAGE 3
#define STAGE_BYTES (2 * BM * BK * 2)   // A + B = 32768
#define SMEM_TOTAL (NSTAGE * STAGE_BYTES)  // 98304

__device__ __align__(1024) __half g_zn[(size_t)NROWS * NC];
__device__ float g_pos[BHALF];
__device__ float g_rs[(size_t)NROWS * NB];
__device__ float g_part[64];
__device__ int g_cnt;   // zero-initialized; self-resetting each run

__device__ __forceinline__ uint32_t smem_u32(const void* p) {
    uint32_t a;
    asm("{ .reg .u64 t; cvta.to.shared.u64 t, %1; cvt.u32.u64 %0, t; }"
        : "=r"(a) : "l"(p));
    return a;
}

#define CP_ASYNC16(dst, src) \
    asm volatile("cp.async.cg.shared.global [%0], [%1], 16;" :: "r"(dst), "l"(src) : "memory")
#define CP_COMMIT() asm volatile("cp.async.commit_group;" ::: "memory")

#define LDSM_X4(r0, r1, r2, r3, addr)                                          \
    asm volatile("ldmatrix.sync.aligned.m8n8.x4.shared.b16 {%0,%1,%2,%3}, [%4];" \
                 : "=r"(r0), "=r"(r1), "=r"(r2), "=r"(r3) : "r"(addr))

#define MMAF16(c, a0, a1, a2, a3, b0, b1)                                      \
    asm volatile("mma.sync.aligned.m16n8k16.row.col.f16.f16.f16.f16 "          \
                 "{%0,%1},{%2,%3,%4,%5},{%6,%7},{%0,%1};"                      \
                 : "+r"((c)[0]), "+r"((c)[1])                                  \
                 : "r"(a0), "r"(a1), "r"(a2), "r"(a3), "r"(b0), "r"(b1))

// ---------------------------------------------------------------------------
// Kernel 1: L2-normalize rows, emit fp16 z. 8 rows/block, 64 threads/row,
// 2 contiguous float4 loads + one 16B store per thread (MLP 2).
// ---------------------------------------------------------------------------
__global__ __launch_bounds__(512) void normalize_kernel(
        const float* __restrict__ z1, const float* __restrict__ z2) {
    const int tid = threadIdx.x;
    const int rl = tid >> 6;            // row within block, 0..7
    const int c = tid & 63;             // 64 threads per row
    const int r = blockIdx.x * 8 + rl;
    const float* row = (r < BHALF) ? (z1 + (size_t)r * NC)
                                   : (z2 + (size_t)(r - BHALF) * NC);
    float4 va = ((const float4*)row)[c * 2];
    float4 vb = ((const float4*)row)[c * 2 + 1];
    float s = va.x * va.x + va.y * va.y + va.z * va.z + va.w * va.w +
              vb.x * vb.x + vb.y * vb.y + vb.z * vb.z + vb.w * vb.w;
#pragma unroll
    for (int o = 16; o; o >>= 1) s += __shfl_xor_sync(0xFFFFFFFFu, s, o);
    __shared__ float ws[16];            // [row][warp-half]
    if ((tid & 31) == 0) ws[(rl << 1) | ((c >> 5) & 1)] = s;
    __syncthreads();
    s = ws[rl << 1] + ws[(rl << 1) | 1];
    float inv = 1.0f / fmaxf(sqrtf(s), 1e-12f);
    uint4 out;
    ((__half2*)&out)[0] = __floats2half2_rn(va.x * inv, va.y * inv);
    ((__half2*)&out)[1] = __floats2half2_rn(va.z * inv, va.w * inv);
    ((__half2*)&out)[2] = __floats2half2_rn(vb.x * inv, vb.y * inv);
    ((__half2*)&out)[3] = __floats2half2_rn(vb.z * inv, vb.w * inv);
    ((uint4*)(g_zn + (size_t)r * NC))[c] = out;
}

// ---------------------------------------------------------------------------
// Kernel 2: fused GEMM + exp + row/col sums + positive capture (upper tri).
// 256 threads = 8 warps in 2(M) x 4(N); warp tile 64x32 via m16n8k16.
// (identical to the 252us R6 kernel)
// ---------------------------------------------------------------------------
__global__ __launch_bounds__(256, 2) void gemm_kernel() {
    extern __shared__ __align__(1024) char smem[];
    const int tid = threadIdx.x;
    const int lane = tid & 31;
    const int w = tid >> 5;
    const int wm = w >> 2;       // 0..1
    const int wn = w & 3;        // 0..3

    int rem = blockIdx.x;
    int bm = 0;
#pragma unroll 1
    while (rem >= (NB - bm)) { rem -= (NB - bm); bm++; }
    const int bn = bm + rem;
    const int r0 = bm * BM;
    const int c0 = bn * BN;
    const uint32_t sbase = smem_u32(smem);

    const int half = tid >> 7;          // 0 = A (rows), 1 = B (cols)
    const int lrow = tid & 127;
    const char* grow = (const char*)g_zn +
        ((size_t)((half ? c0 : r0) + lrow)) * (NC * 2);
    const uint32_t sdst = sbase + (uint32_t)half * (BM * BK * 2) +
                          (uint32_t)lrow * 128u;
    const uint32_t xr = ((uint32_t)lrow & 7u) << 4;

#define ISSUE_STAGE(s_)                                                        \
    do {                                                                       \
        const char* g_ = grow + (s_) * (BK * 2);                               \
        uint32_t d_ = sdst + (uint32_t)((s_) % NSTAGE) * STAGE_BYTES;          \
        _Pragma("unroll")                                                      \
        for (int c_ = 0; c_ < 8; c_++)                                         \
            CP_ASYNC16(d_ + (((uint32_t)c_ * 16u) ^ xr), g_ + c_ * 16);        \
        CP_COMMIT();                                                           \
    } while (0)

    ISSUE_STAGE(0);
    ISSUE_STAGE(1);

    uint32_t addrA[4], xA[4];
    const uint32_t chunkA = ((uint32_t)(lane >> 4)) * 16u;
#pragma unroll
    for (int mi = 0; mi < 4; mi++) {
        int rA = wm * 64 + mi * 16 + (lane & 15);
        addrA[mi] = sbase + (uint32_t)rA * 128u;
        xA[mi] = ((uint32_t)rA & 7u) << 4;
    }
    uint32_t addrB[2], xB[2];
    const uint32_t chunkB = ((uint32_t)((lane >> 3) & 1)) * 16u;
#pragma unroll
    for (int np = 0; np < 2; np++) {
        int rB = wn * 32 + np * 16 + ((lane >> 4) & 1) * 8 + (lane & 7);
        addrB[np] = sbase + (uint32_t)(BM * BK * 2) + (uint32_t)rB * 128u;
        xB[np] = ((uint32_t)rB & 7u) << 4;
    }

    uint32_t acc[4][4][2];   // f16x2 accumulators
#pragma unroll
    for (int mi = 0; mi < 4; mi++)
#pragma unroll
        for (int ni = 0; ni < 4; ni++) {
            acc[mi][ni][0] = 0u;
            acc[mi][ni][1] = 0u;
        }

#pragma unroll 1
    for (int i = 0; i < KITERS; i++) {
        if (i < KITERS - 1)
            asm volatile("cp.async.wait_group 1;" ::: "memory");
        else
            asm volatile("cp.async.wait_group 0;" ::: "memory");
        __syncthreads();
        if (i + 2 < KITERS) ISSUE_STAGE(i + 2);

        const uint32_t sb = (uint32_t)(i % NSTAGE) * STAGE_BYTES;
#pragma unroll
        for (int kk = 0; kk < 4; kk++) {
            const uint32_t kkb = (uint32_t)kk * 32u;
            uint32_t a[4][4], b[2][4];
#pragma unroll
            for (int mi = 0; mi < 4; mi++)
                LDSM_X4(a[mi][0], a[mi][1], a[mi][2], a[mi][3],
                        addrA[mi] + sb + ((kkb | chunkA) ^ xA[mi]));
#pragma unroll
            for (int np = 0; np < 2; np++)
                LDSM_X4(b[np][0], b[np][1], b[np][2], b[np][3],
                        addrB[np] + sb + ((kkb | chunkB) ^ xB[np]));
#pragma unroll
            for (int mi = 0; mi < 4; mi++)
#pragma unroll
                for (int ni = 0; ni < 4; ni++)
                    MMAF16(acc[mi][ni],
                           a[mi][0], a[mi][1], a[mi][2], a[mi][3],
                           b[ni >> 1][(ni & 1) * 2],
                           b[ni >> 1][(ni & 1) * 2 + 1]);
        }
    }

    float vr[4][2];
    float cv[4][2];
#pragma unroll
    for (int i = 0; i < 4; i++) {
        vr[i][0] = vr[i][1] = 0.f;
        cv[i][0] = cv[i][1] = 0.f;
    }

#pragma unroll
    for (int mi = 0; mi < 4; mi++)
#pragma unroll
        for (int ni = 0; ni < 4; ni++)
#pragma unroll
            for (int h = 0; h < 2; h++) {
                float2 f = __half22float2(*(__half2*)&acc[mi][ni][h]);
                int rowg = r0 + wm * 64 + mi * 16 + h * 8 + (lane >> 2);
                int colb = c0 + wn * 32 + ni * 8 + (lane & 3) * 2;
                float v0 = __expf(f.x * 10.0f);
                float v1 = __expf(f.y * 10.0f);
                vr[mi][h] += v0 + v1;
                cv[ni][0] += v0;
                cv[ni][1] += v1;
                if (colb == rowg + BHALF) g_pos[rowg] = v0;
                if (colb + 1 == rowg + BHALF) g_pos[rowg] = v1;
            }
#pragma unroll
    for (int mi = 0; mi < 4; mi++)
#pragma unroll
        for (int h = 0; h < 2; h++) {
            float v = vr[mi][h];
            v += __shfl_xor_sync(0xFFFFFFFFu, v, 1);
            v += __shfl_xor_sync(0xFFFFFFFFu, v, 2);
            vr[mi][h] = v;
        }
#pragma unroll
    for (int ni = 0; ni < 4; ni++)
#pragma unroll
        for (int b = 0; b < 2; b++) {
            float v = cv[ni][b];
            v += __shfl_xor_sync(0xFFFFFFFFu, v, 4);
            v += __shfl_xor_sync(0xFFFFFFFFu, v, 8);
            v += __shfl_xor_sync(0xFFFFFFFFu, v, 16);
            cv[ni][b] = v;
        }

    __syncthreads();
    float* redr = (float*)smem;          // [4 wn][128 rows]
    float* redc = (float*)smem + 512;    // [2 wm][128 cols]
    if ((lane & 3) == 0) {
#pragma unroll
        for (int mi = 0; mi < 4; mi++)
#pragma unroll
            for (int h = 0; h < 2; h++)
                redr[wn * 128 + wm * 64 + mi * 16 + h * 8 + (lane >> 2)] = vr[mi][h];
    }
    if (lane < 4) {
#pragma unroll
        for (int ni = 0; ni < 4; ni++)
#pragma unroll
            for (int b = 0; b < 2; b++)
                redc[wm * 128 + wn * 32 + ni * 8 + lane * 2 + b] = cv[ni][b];
    }
    __syncthreads();
    if (tid < 128) {
        float t = redr[tid] + redr[128 + tid] + redr[256 + tid] + redr[384 + tid];
        g_rs[((size_t)(r0 + tid)) * NB + bn] = t;
    } else if (bm != bn) {
        int t2 = tid - 128;
        float t = redc[t2] + redc[128 + t2];
        g_rs[((size_t)(c0 + t2)) * NB + bm] = t;
    }
}

// ---------------------------------------------------------------------------
// Kernel 3: per-128-row partial loss sums; last block finalizes the scalar.
// Counter self-resets so the kernel is replay-safe under graph capture.
// ---------------------------------------------------------------------------
__global__ void loss_kernel(float* __restrict__ out) {
    int r = blockIdx.x * 128 + threadIdx.x;
    const float4* p4 = (const float4*)&g_rs[(size_t)r * NB];
    float tot = 0.f;
#pragma unroll
    for (int i = 0; i < NB / 4; i++) {
        float4 q = p4[i];
        tot += (q.x + q.y) + (q.z + q.w);
    }
    float p = g_pos[r & (BHALF - 1)];
    float s = logf(tot - p) - logf(p);
#pragma unroll
    for (int o = 16; o; o >>= 1) s += __shfl_xor_sync(0xFFFFFFFFu, s, o);
    __shared__ float ws[4];
    __shared__ int is_last;
    if ((threadIdx.x & 31) == 0) ws[threadIdx.x >> 5] = s;
    __syncthreads();
    if (threadIdx.x == 0) {
        g_part[blockIdx.x] = ws[0] + ws[1] + ws[2] + ws[3];
        __threadfence();
        is_last = (atomicAdd(&g_cnt, 1) == 63) ? 1 : 0;
        if (is_last) g_cnt = 0;   // reset for next graph replay
    }
    __syncthreads();
    if (is_last && threadIdx.x < 64) {
        float v = g_part[threadIdx.x];
#pragma unroll
        for (int o = 16; o; o >>= 1) v += __shfl_xor_sync(0xFFFFFFFFu, v, o);
        __shared__ float h2[2];
        if ((threadIdx.x & 31) == 0) h2[threadIdx.x >> 5] = v;
        __syncwarp();
        __syncthreads();
        if (threadIdx.x == 0)
            out[0] = (h2[0] + h2[1]) / ((float)NROWS * (float)BHALF);
    }
}

extern "C" void kernel_launch(void* const* d_in, const int* in_sizes, int n_in,
                              void* d_out, int out_size) {
    const float* z1 = (const float*)d_in[0];
    const float* z2 = (const float*)d_in[1];
    (void)in_sizes; (void)n_in; (void)out_size;

    cudaFuncSetAttribute(gemm_kernel, cudaFuncAttributeMaxDynamicSharedMemorySize,
                         SMEM_TOTAL);

    normalize_kernel<<<NROWS / 8, 512>>>(z1, z2);
    gemm_kernel<<<NPAIRS, 256, SMEM_TOTAL>>>();
    loss_kernel<<<64, 128>>>((float*)d_out);
}

// round 11
// speedup vs baseline: 2.0284x; 1.0032x over previous
#include <cuda_runtime.h>
#include <cuda_fp16.h>
#include <math.h>
#include <stdint.h>

// NT-Xent loss on GB300, f16-acc HMMA + symmetry. GEMM and fused loss are
// byte-identical to the 188.5us R10 version (also serves as a stability
// re-bench). Normalize rebuilt warp-per-row: MLP 4, shuffle-only reduction,
// no smem, no __syncthreads.

#define NROWS 8192
#define NC    512
#define BHALF 4096
#define NB    (NROWS / 128)         // 64
#define NPAIRS (NB * (NB + 1) / 2)  // 2080

#define BM 128
#define BN 128
#define BK 64
#define KITERS (NC / BK)        // 8
#define NSTAGE 3
#define STAGE_BYTES (2 * BM * BK * 2)   // A + B = 32768
#define SMEM_TOTAL (NSTAGE * STAGE_BYTES)  // 98304

__device__ __align__(1024) __half g_zn[(size_t)NROWS * NC];
__device__ float g_pos[BHALF];
__device__ float g_rs[(size_t)NROWS * NB];
__device__ float g_part[64];
__device__ int g_cnt;   // zero-initialized; self-resetting each run

__device__ __forceinline__ uint32_t smem_u32(const void* p) {
    uint32_t a;
    asm("{ .reg .u64 t; cvta.to.shared.u64 t, %1; cvt.u32.u64 %0, t; }"
        : "=r"(a) : "l"(p));
    return a;
}

#define CP_ASYNC16(dst, src) \
    asm volatile("cp.async.cg.shared.global [%0], [%1], 16;" :: "r"(dst), "l"(src) : "memory")
#define CP_COMMIT() asm volatile("cp.async.commit_group;" ::: "memory")

#define LDSM_X4(r0, r1, r2, r3, addr)                                          \
    asm volatile("ldmatrix.sync.aligned.m8n8.x4.shared.b16 {%0,%1,%2,%3}, [%4];" \
                 : "=r"(r0), "=r"(r1), "=r"(r2), "=r"(r3) : "r"(addr))

#define MMAF16(c, a0, a1, a2, a3, b0, b1)                                      \
    asm volatile("mma.sync.aligned.m16n8k16.row.col.f16.f16.f16.f16 "          \
                 "{%0,%1},{%2,%3,%4,%5},{%6,%7},{%0,%1};"                      \
                 : "+r"((c)[0]), "+r"((c)[1])                                  \
                 : "r"(a0), "r"(a1), "r"(a2), "r"(a3), "r"(b0), "r"(b1))

// ---------------------------------------------------------------------------
// Kernel 1: L2-normalize rows, emit fp16 z. One warp per row: 4 coalesced
// float4 loads per lane (MLP 4), shuffle-only reduce, no smem/barriers.
// ---------------------------------------------------------------------------
__global__ __launch_bounds__(512) void normalize_kernel(
        const float* __restrict__ z1, const float* __restrict__ z2) {
    const int lane = threadIdx.x & 31;
    const int r = blockIdx.x * 16 + (threadIdx.x >> 5);
    const float* row = (r < BHALF) ? (z1 + (size_t)r * NC)
                                   : (z2 + (size_t)(r - BHALF) * NC);
    float4 v[4];
#pragma unroll
    for (int i = 0; i < 4; i++) v[i] = ((const float4*)row)[lane + 32 * i];
    float s = 0.f;
#pragma unroll
    for (int i = 0; i < 4; i++)
        s += v[i].x * v[i].x + v[i].y * v[i].y + v[i].z * v[i].z + v[i].w * v[i].w;
#pragma unroll
    for (int o = 16; o; o >>= 1) s += __shfl_xor_sync(0xFFFFFFFFu, s, o);
    float inv = 1.0f / fmaxf(sqrtf(s), 1e-12f);
    uint4* dst = (uint4*)(g_zn + (size_t)r * NC);
#pragma unroll
    for (int i = 0; i < 4; i++) {
        uint4 out;
        ((__half2*)&out)[0] = __floats2half2_rn(v[i].x * inv, v[i].y * inv);
        ((__half2*)&out)[1] = __floats2half2_rn(v[i].z * inv, v[i].w * inv);
        ((__half2*)&out)[2] = __floats2half2_rn(0.f, 0.f);   // overwritten below
        ((__half2*)&out)[3] = __floats2half2_rn(0.f, 0.f);
        // pack 8 halves from one float4 pair: we only have 4 floats -> 8B.
        // Store as 8-byte chunks instead:
        ((uint2*)dst)[lane + 32 * i] = make_uint2(out.x, out.y);
    }
}

// ---------------------------------------------------------------------------
// Kernel 2: fused GEMM + exp + row/col sums + positive capture (upper tri).
// 256 threads = 8 warps in 2(M) x 4(N); warp tile 64x32 via m16n8k16.
// (byte-identical to the 188.5us R10 kernel)
// ---------------------------------------------------------------------------
__global__ __launch_bounds__(256, 2) void gemm_kernel() {
    extern __shared__ __align__(1024) char smem[];
    const int tid = threadIdx.x;
    const int lane = tid & 31;
    const int w = tid >> 5;
    const int wm = w >> 2;       // 0..1
    const int wn = w & 3;        // 0..3

    int rem = blockIdx.x;
    int bm = 0;
#pragma unroll 1
    while (rem >= (NB - bm)) { rem -= (NB - bm); bm++; }
    const int bn = bm + rem;
    const int r0 = bm * BM;
    const int c0 = bn * BN;
    const uint32_t sbase = smem_u32(smem);

    const int half = tid >> 7;          // 0 = A (rows), 1 = B (cols)
    const int lrow = tid & 127;
    const char* grow = (const char*)g_zn +
        ((size_t)((half ? c0 : r0) + lrow)) * (NC * 2);
    const uint32_t sdst = sbase + (uint32_t)half * (BM * BK * 2) +
                          (uint32_t)lrow * 128u;
    const uint32_t xr = ((uint32_t)lrow & 7u) << 4;

#define ISSUE_STAGE(s_)                                                        \
    do {                                                                       \
        const char* g_ = grow + (s_) * (BK * 2);                               \
        uint32_t d_ = sdst + (uint32_t)((s_) % NSTAGE) * STAGE_BYTES;          \
        _Pragma("unroll")                                                      \
        for (int c_ = 0; c_ < 8; c_++)                                         \
            CP_ASYNC16(d_ + (((uint32_t)c_ * 16u) ^ xr), g_ + c_ * 16);        \
        CP_COMMIT();                                                           \
    } while (0)

    ISSUE_STAGE(0);
    ISSUE_STAGE(1);

    uint32_t addrA[4], xA[4];
    const uint32_t chunkA = ((uint32_t)(lane >> 4)) * 16u;
#pragma unroll
    for (int mi = 0; mi < 4; mi++) {
        int rA = wm * 64 + mi * 16 + (lane & 15);
        addrA[mi] = sbase + (uint32_t)rA * 128u;
        xA[mi] = ((uint32_t)rA & 7u) << 4;
    }
    uint32_t addrB[2], xB[2];
    const uint32_t chunkB = ((uint32_t)((lane >> 3) & 1)) * 16u;
#pragma unroll
    for (int np = 0; np < 2; np++) {
        int rB = wn * 32 + np * 16 + ((lane >> 4) & 1) * 8 + (lane & 7);
        addrB[np] = sbase + (uint32_t)(BM * BK * 2) + (uint32_t)rB * 128u;
        xB[np] = ((uint32_t)rB & 7u) << 4;
    }

    uint32_t acc[4][4][2];   // f16x2 accumulators
#pragma unroll
    for (int mi = 0; mi < 4; mi++)
#pragma unroll
        for (int ni = 0; ni < 4; ni++) {
            acc[mi][ni][0] = 0u;
            acc[mi][ni][1] = 0u;
        }

#pragma unroll 1
    for (int i = 0; i < KITERS; i++) {
        if (i < KITERS - 1)
            asm volatile("cp.async.wait_group 1;" ::: "memory");
        else
            asm volatile("cp.async.wait_group 0;" ::: "memory");
        __syncthreads();
        if (i + 2 < KITERS) ISSUE_STAGE(i + 2);

        const uint32_t sb = (uint32_t)(i % NSTAGE) * STAGE_BYTES;
#pragma unroll
        for (int kk = 0; kk < 4; kk++) {
            const uint32_t kkb = (uint32_t)kk * 32u;
            uint32_t a[4][4], b[2][4];
#pragma unroll
            for (int mi = 0; mi < 4; mi++)
                LDSM_X4(a[mi][0], a[mi][1], a[mi][2], a[mi][3],
                        addrA[mi] + sb + ((kkb | chunkA) ^ xA[mi]));
#pragma unroll
            for (int np = 0; np < 2; np++)
                LDSM_X4(b[np][0], b[np][1], b[np][2], b[np][3],
                        addrB[np] + sb + ((kkb | chunkB) ^ xB[np]));
#pragma unroll
            for (int mi = 0; mi < 4; mi++)
#pragma unroll
                for (int ni = 0; ni < 4; ni++)
                    MMAF16(acc[mi][ni],
                           a[mi][0], a[mi][1], a[mi][2], a[mi][3],
                           b[ni >> 1][(ni & 1) * 2],
                           b[ni >> 1][(ni & 1) * 2 + 1]);
        }
    }

    float vr[4][2];
    float cv[4][2];
#pragma unroll
    for (int i = 0; i < 4; i++) {
        vr[i][0] = vr[i][1] = 0.f;
        cv[i][0] = cv[i][1] = 0.f;
    }

#pragma unroll
    for (int mi = 0; mi < 4; mi++)
#pragma unroll
        for (int ni = 0; ni < 4; ni++)
#pragma unroll
            for (int h = 0; h < 2; h++) {
                float2 f = __half22float2(*(__half2*)&acc[mi][ni][h]);
                int rowg = r0 + wm * 64 + mi * 16 + h * 8 + (lane >> 2);
                int colb = c0 + wn * 32 + ni * 8 + (lane & 3) * 2;
                float v0 = __expf(f.x * 10.0f);
                float v1 = __expf(f.y * 10.0f);
                vr[mi][h] += v0 + v1;
                cv[ni][0] += v0;
                cv[ni][1] += v1;
                if (colb == rowg + BHALF) g_pos[rowg] = v0;
                if (colb + 1 == rowg + BHALF) g_pos[rowg] = v1;
            }
#pragma unroll
    for (int mi = 0; mi < 4; mi++)
#pragma unroll
        for (int h = 0; h < 2; h++) {
            float v = vr[mi][h];
            v += __shfl_xor_sync(0xFFFFFFFFu, v, 1);
            v += __shfl_xor_sync(0xFFFFFFFFu, v, 2);
            vr[mi][h] = v;
        }
#pragma unroll
    for (int ni = 0; ni < 4; ni++)
#pragma unroll
        for (int b = 0; b < 2; b++) {
            float v = cv[ni][b];
            v += __shfl_xor_sync(0xFFFFFFFFu, v, 4);
            v += __shfl_xor_sync(0xFFFFFFFFu, v, 8);
            v += __shfl_xor_sync(0xFFFFFFFFu, v, 16);
            cv[ni][b] = v;
        }

    __syncthreads();
    float* redr = (float*)smem;          // [4 wn][128 rows]
    float* redc = (float*)smem + 512;    // [2 wm][128 cols]
    if ((lane & 3) == 0) {
#pragma unroll
        for (int mi = 0; mi < 4; mi++)
#pragma unroll
            for (int h = 0; h < 2; h++)
                redr[wn * 128 + wm * 64 + mi * 16 + h * 8 + (lane >> 2)] = vr[mi][h];
    }
    if (lane < 4) {
#pragma unroll
        for (int ni = 0; ni < 4; ni++)
#pragma unroll
            for (int b = 0; b < 2; b++)
                redc[wm * 128 + wn * 32 + ni * 8 + lane * 2 + b] = cv[ni][b];
    }
    __syncthreads();
    if (tid < 128) {
        float t = redr[tid] + redr[128 + tid] + redr[256 + tid] + redr[384 + tid];
        g_rs[((size_t)(r0 + tid)) * NB + bn] = t;
    } else if (bm != bn) {
        int t2 = tid - 128;
        float t = redc[t2] + redc[128 + t2];
        g_rs[((size_t)(c0 + t2)) * NB + bm] = t;
    }
}

// ---------------------------------------------------------------------------
// Kernel 3: per-128-row partial loss sums; last block finalizes the scalar.
// (byte-identical to R10)
// ---------------------------------------------------------------------------
__global__ void loss_kernel(float* __restrict__ out) {
    int r = blockIdx.x * 128 + threadIdx.x;
    const float4* p4 = (const float4*)&g_rs[(size_t)r * NB];
    float tot = 0.f;
#pragma unroll
    for (int i = 0; i < NB / 4; i++) {
        float4 q = p4[i];
        tot += (q.x + q.y) + (q.z + q.w);
    }
    float p = g_pos[r & (BHALF - 1)];
    float s = logf(tot - p) - logf(p);
#pragma unroll
    for (int o = 16; o; o >>= 1) s += __shfl_xor_sync(0xFFFFFFFFu, s, o);
    __shared__ float ws[4];
    __shared__ int is_last;
    if ((threadIdx.x & 31) == 0) ws[threadIdx.x >> 5] = s;
    __syncthreads();
    if (threadIdx.x == 0) {
        g_part[blockIdx.x] = ws[0] + ws[1] + ws[2] + ws[3];
        __threadfence();
        is_last = (atomicAdd(&g_cnt, 1) == 63) ? 1 : 0;
        if (is_last) g_cnt = 0;   // reset for next graph replay
    }
    __syncthreads();
    if (is_last && threadIdx.x < 64) {
        float v = g_part[threadIdx.x];
#pragma unroll
        for (int o = 16; o; o >>= 1) v += __shfl_xor_sync(0xFFFFFFFFu, v, o);
        __shared__ float h2[2];
        if ((threadIdx.x & 31) == 0) h2[threadIdx.x >> 5] = v;
        __syncwarp();
        __syncthreads();
        if (threadIdx.x == 0)
            out[0] = (h2[0] + h2[1]) / ((float)NROWS * (float)BHALF);
    }
}

extern "C" void kernel_launch(void* const* d_in, const int* in_sizes, int n_in,
                              void* d_out, int out_size) {
    const float* z1 = (const float*)d_in[0];
    const float* z2 = (const float*)d_in[1];
    (void)in_sizes; (void)n_in; (void)out_size;

    cudaFuncSetAttribute(gemm_kernel, cudaFuncAttributeMaxDynamicSharedMemorySize,
                         SMEM_TOTAL);

    normalize_kernel<<<NROWS / 16, 512>>>(z1, z2);
    gemm_kernel<<<NPAIRS, 256, SMEM_TOTAL>>>();
    loss_kernel<<<64, 128>>>((float*)d_out);
}

// round 12
// speedup vs baseline: 2.1632x; 1.0665x over previous
#include <cuda_runtime.h>
#include <cuda_fp16.h>
#include <math.h>
#include <stdint.h>

// NT-Xent loss on GB300, f16-acc HMMA + symmetry. R12: occupancy 3 via
// 2-stage cp.async pipeline (64KB smem/CTA) -> 444 CTA slots -> wave
// utilization 93.7% vs 87.9% at occ2. Register-compacted ldmatrix addressing
// (single swizzle reg + immediate strides) to fit the 85-reg occ3 cap.
// Normalize / loss kernels byte-identical to the 187.9us R11 version.

#define NROWS 8192
#define NC    512
#define BHALF 4096
#define NB    (NROWS / 128)         // 64
#define NPAIRS (NB * (NB + 1) / 2)  // 2080

#define BM 128
#define BN 128
#define BK 64
#define KITERS (NC / BK)        // 8
#define NSTAGE 2
#define STAGE_BYTES (2 * BM * BK * 2)   // A + B = 32768
#define SMEM_TOTAL (NSTAGE * STAGE_BYTES)  // 65536

__device__ __align__(1024) __half g_zn[(size_t)NROWS * NC];
__device__ float g_pos[BHALF];
__device__ float g_rs[(size_t)NROWS * NB];
__device__ float g_part[64];
__device__ int g_cnt;   // zero-initialized; self-resetting each run

__device__ __forceinline__ uint32_t smem_u32(const void* p) {
    uint32_t a;
    asm("{ .reg .u64 t; cvta.to.shared.u64 t, %1; cvt.u32.u64 %0, t; }"
        : "=r"(a) : "l"(p));
    return a;
}

#define CP_ASYNC16(dst, src) \
    asm volatile("cp.async.cg.shared.global [%0], [%1], 16;" :: "r"(dst), "l"(src) : "memory")
#define CP_COMMIT() asm volatile("cp.async.commit_group;" ::: "memory")

#define LDSM_X4(r0, r1, r2, r3, addr)                                          \
    asm volatile("ldmatrix.sync.aligned.m8n8.x4.shared.b16 {%0,%1,%2,%3}, [%4];" \
                 : "=r"(r0), "=r"(r1), "=r"(r2), "=r"(r3) : "r"(addr))

#define MMAF16(c, a0, a1, a2, a3, b0, b1)                                      \
    asm volatile("mma.sync.aligned.m16n8k16.row.col.f16.f16.f16.f16 "          \
                 "{%0,%1},{%2,%3,%4,%5},{%6,%7},{%0,%1};"                      \
                 : "+r"((c)[0]), "+r"((c)[1])                                  \
                 : "r"(a0), "r"(a1), "r"(a2), "r"(a3), "r"(b0), "r"(b1))

// ---------------------------------------------------------------------------
// Kernel 1: L2-normalize rows, emit fp16 z. One warp per row, MLP 4,
// shuffle-only reduction. (identical to R11)
// ---------------------------------------------------------------------------
__global__ __launch_bounds__(512) void normalize_kernel(
        const float* __restrict__ z1, const float* __restrict__ z2) {
    const int lane = threadIdx.x & 31;
    const int r = blockIdx.x * 16 + (threadIdx.x >> 5);
    const float* row = (r < BHALF) ? (z1 + (size_t)r * NC)
                                   : (z2 + (size_t)(r - BHALF) * NC);
    float4 v[4];
#pragma unroll
    for (int i = 0; i < 4; i++) v[i] = ((const float4*)row)[lane + 32 * i];
    float s = 0.f;
#pragma unroll
    for (int i = 0; i < 4; i++)
        s += v[i].x * v[i].x + v[i].y * v[i].y + v[i].z * v[i].z + v[i].w * v[i].w;
#pragma unroll
    for (int o = 16; o; o >>= 1) s += __shfl_xor_sync(0xFFFFFFFFu, s, o);
    float inv = 1.0f / fmaxf(sqrtf(s), 1e-12f);
    uint2* dst = (uint2*)(g_zn + (size_t)r * NC);
#pragma unroll
    for (int i = 0; i < 4; i++) {
        uint2 out;
        ((__half2*)&out)[0] = __floats2half2_rn(v[i].x * inv, v[i].y * inv);
        ((__half2*)&out)[1] = __floats2half2_rn(v[i].z * inv, v[i].w * inv);
        dst[lane + 32 * i] = out;
    }
}

// ---------------------------------------------------------------------------
// Kernel 2: fused GEMM + exp + row/col sums + positive capture (upper tri).
// 256 threads = 8 warps in 2(M) x 4(N); warp tile 64x32 via m16n8k16.
// 2-stage pipeline, occupancy 3.
// ---------------------------------------------------------------------------
__global__ __launch_bounds__(256, 3) void gemm_kernel() {
    extern __shared__ __align__(1024) char smem[];
    const int tid = threadIdx.x;
    const int lane = tid & 31;
    const int w = tid >> 5;
    const int wm = w >> 2;       // 0..1
    const int wn = w & 3;        // 0..3

    int rem = blockIdx.x;
    int bm = 0;
#pragma unroll 1
    while (rem >= (NB - bm)) { rem -= (NB - bm); bm++; }
    const int bn = bm + rem;
    const int r0 = bm * BM;
    const int c0 = bn * BN;
    const uint32_t sbase = smem_u32(smem);

    // ---- cp.async: 256 threads -> 256 tile rows (128 A + 128 B) ----
    const int half = tid >> 7;
    const int lrow = tid & 127;
    const char* grow = (const char*)g_zn +
        ((size_t)((half ? c0 : r0) + lrow)) * (NC * 2);
    const uint32_t sdst = sbase + (uint32_t)half * (BM * BK * 2) +
                          (uint32_t)lrow * 128u;
    const uint32_t xr = ((uint32_t)lrow & 7u) << 4;

#define ISSUE_STAGE(s_)                                                        \
    do {                                                                       \
        const char* g_ = grow + (s_) * (BK * 2);                               \
        uint32_t d_ = sdst + (uint32_t)((s_) & 1) * STAGE_BYTES;               \
        _Pragma("unroll")                                                      \
        for (int c_ = 0; c_ < 8; c_++)                                         \
            CP_ASYNC16(d_ + (((uint32_t)c_ * 16u) ^ xr), g_ + c_ * 16);        \
        CP_COMMIT();                                                           \
    } while (0)

    ISSUE_STAGE(0);

    // ---- register-compacted ldmatrix addressing ----
    // rowA = wm*64 + mi*16 + (lane&15): (rowA&7) is mi-invariant -> one xA.
    const uint32_t xA = ((uint32_t)(lane & 7)) << 4;
    const uint32_t chunkA = ((uint32_t)(lane >> 4)) * 16u;
    const uint32_t aBase = sbase +
        (uint32_t)(wm * 64 + (lane & 15)) * 128u;       // + mi*2048
    // rowB = wn*32 + np*16 + ((lane>>4)&1)*8 + (lane&7): (rowB&7) = lane&7.
    const uint32_t xB = xA;
    const uint32_t chunkB = ((uint32_t)((lane >> 3) & 1)) * 16u;
    const uint32_t bBase = sbase + (uint32_t)(BM * BK * 2) +
        (uint32_t)(wn * 32 + ((lane >> 4) & 1) * 8 + (lane & 7)) * 128u;

    uint32_t acc[4][4][2];   // f16x2 accumulators
#pragma unroll
    for (int mi = 0; mi < 4; mi++)
#pragma unroll
        for (int ni = 0; ni < 4; ni++) {
            acc[mi][ni][0] = 0u;
            acc[mi][ni][1] = 0u;
        }

    // ---- mainloop: wait stage i, sync, prefetch stage i+1, compute ----
#pragma unroll 1
    for (int i = 0; i < KITERS; i++) {
        asm volatile("cp.async.wait_group 0;" ::: "memory");
        __syncthreads();
        if (i + 1 < KITERS) ISSUE_STAGE(i + 1);

        const uint32_t sb = (uint32_t)(i & 1) * STAGE_BYTES;
#pragma unroll
        for (int kk = 0; kk < 4; kk++) {
            const uint32_t kkb = (uint32_t)kk * 32u;
            const uint32_t offA = sb + ((kkb | chunkA) ^ xA);
            const uint32_t offB = sb + ((kkb | chunkB) ^ xB);
            uint32_t a[4][4], b[2][4];
#pragma unroll
            for (int mi = 0; mi < 4; mi++)
                LDSM_X4(a[mi][0], a[mi][1], a[mi][2], a[mi][3],
                        aBase + (uint32_t)(mi * 2048) + offA);
#pragma unroll
            for (int np = 0; np < 2; np++)
                LDSM_X4(b[np][0], b[np][1], b[np][2], b[np][3],
                        bBase + (uint32_t)(np * 2048) + offB);
#pragma unroll
            for (int mi = 0; mi < 4; mi++)
#pragma unroll
                for (int ni = 0; ni < 4; ni++)
                    MMAF16(acc[mi][ni],
                           a[mi][0], a[mi][1], a[mi][2], a[mi][3],
                           b[ni >> 1][(ni & 1) * 2],
                           b[ni >> 1][(ni & 1) * 2 + 1]);
        }
    }

    // ---- epilogue: promote, exp, positive capture, row/col partials ----
    float vr[4][2];
    float cv[4][2];
#pragma unroll
    for (int i = 0; i < 4; i++) {
        vr[i][0] = vr[i][1] = 0.f;
        cv[i][0] = cv[i][1] = 0.f;
    }

#pragma unroll
    for (int mi = 0; mi < 4; mi++)
#pragma unroll
        for (int ni = 0; ni < 4; ni++)
#pragma unroll
            for (int h = 0; h < 2; h++) {
                float2 f = __half22float2(*(__half2*)&acc[mi][ni][h]);
                int rowg = r0 + wm * 64 + mi * 16 + h * 8 + (lane >> 2);
                int colb = c0 + wn * 32 + ni * 8 + (lane & 3) * 2;
                float v0 = __expf(f.x * 10.0f);
                float v1 = __expf(f.y * 10.0f);
                vr[mi][h] += v0 + v1;
                cv[ni][0] += v0;
                cv[ni][1] += v1;
                if (colb == rowg + BHALF) g_pos[rowg] = v0;
                if (colb + 1 == rowg + BHALF) g_pos[rowg] = v1;
            }
#pragma unroll
    for (int mi = 0; mi < 4; mi++)
#pragma unroll
        for (int h = 0; h < 2; h++) {
            float v = vr[mi][h];
            v += __shfl_xor_sync(0xFFFFFFFFu, v, 1);
            v += __shfl_xor_sync(0xFFFFFFFFu, v, 2);
            vr[mi][h] = v;
        }
#pragma unroll
    for (int ni = 0; ni < 4; ni++)
#pragma unroll
        for (int b = 0; b < 2; b++) {
            float v = cv[ni][b];
            v += __shfl_xor_sync(0xFFFFFFFFu, v, 4);
            v += __shfl_xor_sync(0xFFFFFFFFu, v, 8);
            v += __shfl_xor_sync(0xFFFFFFFFu, v, 16);
            cv[ni][b] = v;
        }

    __syncthreads();
    float* redr = (float*)smem;          // [4 wn][128 rows]
    float* redc = (float*)smem + 512;    // [2 wm][128 cols]
    if ((lane & 3) == 0) {
#pragma unroll
        for (int mi = 0; mi < 4; mi++)
#pragma unroll
            for (int h = 0; h < 2; h++)
                redr[wn * 128 + wm * 64 + mi * 16 + h * 8 + (lane >> 2)] = vr[mi][h];
    }
    if (lane < 4) {
#pragma unroll
        for (int ni = 0; ni < 4; ni++)
#pragma unroll
            for (int b = 0; b < 2; b++)
                redc[wm * 128 + wn * 32 + ni * 8 + lane * 2 + b] = cv[ni][b];
    }
    __syncthreads();
    if (tid < 128) {
        float t = redr[tid] + redr[128 + tid] + redr[256 + tid] + redr[384 + tid];
        g_rs[((size_t)(r0 + tid)) * NB + bn] = t;
    } else if (bm != bn) {
        int t2 = tid - 128;
        float t = redc[t2] + redc[128 + t2];
        g_rs[((size_t)(c0 + t2)) * NB + bm] = t;
    }
}

// ---------------------------------------------------------------------------
// Kernel 3: per-128-row partial loss sums; last block finalizes the scalar.
// (identical to R11)
// ---------------------------------------------------------------------------
__global__ void loss_kernel(float* __restrict__ out) {
    int r = blockIdx.x * 128 + threadIdx.x;
    const float4* p4 = (const float4*)&g_rs[(size_t)r * NB];
    float tot = 0.f;
#pragma unroll
    for (int i = 0; i < NB / 4; i++) {
        float4 q = p4[i];
        tot += (q.x + q.y) + (q.z + q.w);
    }
    float p = g_pos[r & (BHALF - 1)];
    float s = logf(tot - p) - logf(p);
#pragma unroll
    for (int o = 16; o; o >>= 1) s += __shfl_xor_sync(0xFFFFFFFFu, s, o);
    __shared__ float ws[4];
    __shared__ int is_last;
    if ((threadIdx.x & 31) == 0) ws[threadIdx.x >> 5] = s;
    __syncthreads();
    if (threadIdx.x == 0) {
        g_part[blockIdx.x] = ws[0] + ws[1] + ws[2] + ws[3];
        __threadfence();
        is_last = (atomicAdd(&g_cnt, 1) == 63) ? 1 : 0;
        if (is_last) g_cnt = 0;   // reset for next graph replay
    }
    __syncthreads();
    if (is_last && threadIdx.x < 64) {
        float v = g_part[threadIdx.x];
#pragma unroll
        for (int o = 16; o; o >>= 1) v += __shfl_xor_sync(0xFFFFFFFFu, v, o);
        __shared__ float h2[2];
        if ((threadIdx.x & 31) == 0) h2[threadIdx.x >> 5] = v;
        __syncwarp();
        __syncthreads();
        if (threadIdx.x == 0)
            out[0] = (h2[0] + h2[1]) / ((float)NROWS * (float)BHALF);
    }
}

extern "C" void kernel_launch(void* const* d_in, const int* in_sizes, int n_in,
                              void* d_out, int out_size) {
    const float* z1 = (const float*)d_in[0];
    const float* z2 = (const float*)d_in[1];
    (void)in_sizes; (void)n_in; (void)out_size;

    cudaFuncSetAttribute(gemm_kernel, cudaFuncAttributeMaxDynamicSharedMemorySize,
                         SMEM_TOTAL);

    normalize_kernel<<<NROWS / 16, 512>>>(z1, z2);
    gemm_kernel<<<NPAIRS, 256, SMEM_TOTAL>>>();
    loss_kernel<<<64, 128>>>((float*)d_out);
}